// round 11
// baseline (speedup 1.0000x reference)
#include <cuda_runtime.h>
#include <math.h>

#define NC 19
#define ND 256
#define NB 8
#define HW 16384              // 128*128
#define NPIX (NB*HW)          // 131072
#define NCHUNK 8
#define DCH (ND/NCHUNK)       // 32
#define EPS 1e-8f

// ---------------- static scratch ----------------
__device__ float g_S[NC*ND];
__device__ float g_counts[NC];
__device__ float g_centers[NC*ND];
__device__ float g_ncen[NC];
__device__ unsigned char g_lab8[NPIX];
__device__ float g_dotp[NCHUNK*NPIX];   // 4 MB
__device__ float g_nsqp[NCHUNK*NPIX];   // 4 MB
__device__ float g_percls[NC];
__device__ float g_diff;

// ---------------- kernel 0a: zero g_counts / g_diff (must precede k_prep) ----------------
__global__ void k_zero_counts() {
    if (threadIdx.x < NC) g_counts[threadIdx.x] = 0.f;
    if (threadIdx.x == NC) g_diff = 0.f;
}

// ---------------- kernel 0b: prep — zero accum, pack labels, histogram ----------------
__global__ __launch_bounds__(256) void k_prep(const int4* __restrict__ T) {
    __shared__ int h[NC];
    const int t = threadIdx.x;
    if (t < NC) h[t] = 0;
    __syncthreads();
    const int i = blockIdx.x * 256 + t;          // 32768 int4s total
    int4 l = T[i];
    ((uchar4*)g_lab8)[i] = make_uchar4((unsigned char)l.x, (unsigned char)l.y,
                                       (unsigned char)l.z, (unsigned char)l.w);
    atomicAdd(&h[l.x], 1); atomicAdd(&h[l.y], 1);
    atomicAdd(&h[l.z], 1); atomicAdd(&h[l.w], 1);
    if (blockIdx.x == 0) {                       // zero g_S / g_percls (consumed by later launches)
        for (int k = t; k < NC*ND; k += 256) g_S[k] = 0.f;
        if (t < NC) g_percls[t] = 0.f;
    }
    __syncthreads();
    if (t < NC) atomicAdd(&g_counts[t], (float)h[t]);
}

// ---------------- kernel 1: class sums, lane-private smem bins ----------------
__global__ __launch_bounds__(256) void k_pass1(const float4* __restrict__ X) {
    __shared__ float sbin[8*NC*32];       // 19456 B
    __shared__ float red[8*NC];
    const int t    = threadIdx.x;
    const int lane = t & 31;
    const int w    = t >> 5;
    const int b    = blockIdx.x >> 8;
    const int d    = blockIdx.x & 255;

    for (int i = t; i < 8*NC*32; i += 256) sbin[i] = 0.f;
    __syncthreads();

    const float4* plane = X + (size_t)(b*ND + d) * (HW/4);
    const uchar4* labs  = (const uchar4*)g_lab8 + (size_t)b * (HW/4);
    float* mybin = sbin + w*(NC*32) + lane;

    #pragma unroll 4
    for (int k = 0; k < 16; k++) {
        float4 v = plane[k*256 + t];
        uchar4 L = labs[k*256 + t];
        mybin[(int)L.x * 32] += v.x;
        mybin[(int)L.y * 32] += v.y;
        mybin[(int)L.z * 32] += v.z;
        mybin[(int)L.w * 32] += v.w;
    }
    __syncthreads();

    if (t < 8*NC) {
        const float* row = sbin + t*32;
        float s = 0.f;
        #pragma unroll
        for (int k = 0; k < 32; k++) s += row[(k + t) & 31];
        red[t] = s;
    }
    __syncthreads();
    if (t < NC) {
        float s = 0.f;
        #pragma unroll
        for (int ww = 0; ww < 8; ww++) s += red[ww*NC + t];
        atomicAdd(&g_S[t*ND + d], s);
    }
}

// ---------------- kernel 2: self-contained centers + norms + diff_loss ----------------
// grid=19; each block recomputes ALL centers locally from g_S (L2-resident),
// writes out its own center row + norm, and its diff contribution.
__global__ __launch_bounds__(256) void k_diff() {
    __shared__ float cen[NC][ND+1];   // ~19.5 KB
    __shared__ float cnt_s[NC];
    __shared__ float nrm[NC];
    __shared__ float acc[8];
    const int i    = blockIdx.x;
    const int tid  = threadIdx.x;     // == d index
    const int lane = tid & 31;
    const int w    = tid >> 5;

    if (tid < NC) cnt_s[tid] = g_counts[tid];
    if (tid < 8) acc[tid] = 0.f;
    __syncthreads();
    #pragma unroll
    for (int c = 0; c < NC; c++)
        cen[c][tid] = g_S[c*ND + tid] / fmaxf(cnt_s[c], 1.f);
    __syncthreads();

    // norms: warp w handles classes w, w+8, w+16
    for (int c = w; c < NC; c += 8) {
        float s = 0.f;
        #pragma unroll
        for (int dd = lane; dd < ND; dd += 32) { float v = cen[c][dd]; s += v*v; }
        #pragma unroll
        for (int o = 16; o; o >>= 1) s += __shfl_xor_sync(0xFFFFFFFFu, s, o);
        if (lane == 0) nrm[c] = sqrtf(s);
    }
    __syncthreads();

    // publish own row for k_pass2 / k_finalpix
    g_centers[i*ND + tid] = cen[i][tid];
    if (tid == 0) g_ncen[i] = nrm[i];

    const float ni = nrm[i];
    float mysum = 0.f;
    for (int j = w; j < NC; j += 8) {
        float dot = 0.f;
        #pragma unroll
        for (int dd = lane; dd < ND; dd += 32) dot += cen[i][dd] * cen[j][dd];
        #pragma unroll
        for (int o = 16; o; o >>= 1) dot += __shfl_xor_sync(0xFFFFFFFFu, dot, o);
        if (lane == 0) {
            float s = dot / fmaxf(ni * nrm[j], EPS);
            mysum += (i == j) ? (1.f - s) : fmaxf(s, 0.f);
        }
    }
    if (lane == 0) acc[w] = mysum;
    __syncthreads();
    if (tid == 0 && cnt_s[i] > 0.f) {
        float tot = acc[0]+acc[1]+acc[2]+acc[3]+acc[4]+acc[5]+acc[6]+acc[7];
        atomicAdd(&g_diff, tot / (float)NC);
    }
}

// ---------------- kernel 3: per-pixel partial dot & normsq over a D-chunk ----------------
// 8 pixels per thread (2 float4 loads / dd) for deeper MLP; 1024 blocks x 128 thr
__global__ __launch_bounds__(128) void k_pass2(const float4* __restrict__ X,
                                               const int4* __restrict__ T) {
    __shared__ float csh[NC*33];
    const int tid   = threadIdx.x;
    const int chunk = blockIdx.x & (NCHUNK-1);
    const int tile  = blockIdx.x >> 3;           // 0..127, 1024 px each
    const int b     = tile >> 4;                 // 16 tiles per batch
    const int px0   = ((tile & 15) << 10) + (tid << 3);

    for (int i = tid; i < NC*DCH; i += 128) {
        int c = i / DCH, dd = i - c*DCH;
        csh[c*33 + dd] = g_centers[c*ND + chunk*DCH + dd];
    }
    __syncthreads();

    const int4 l0 = T[((size_t)b*HW + px0) >> 2];
    const int4 l1 = T[(((size_t)b*HW + px0) >> 2) + 1];
    const int la0=l0.x*33, lb0=l0.y*33, lc0=l0.z*33, ld0=l0.w*33;
    const int la1=l1.x*33, lb1=l1.y*33, lc1=l1.z*33, ld1=l1.w*33;
    const float4* base = X + (size_t)(b*ND + chunk*DCH)*(HW/4) + (px0 >> 2);

    float d0x=0,d0y=0,d0z=0,d0w=0, n0x=0,n0y=0,n0z=0,n0w=0;
    float d1x=0,d1y=0,d1z=0,d1w=0, n1x=0,n1y=0,n1z=0,n1w=0;
    #pragma unroll 4
    for (int dd = 0; dd < DCH; dd++) {
        float4 v0 = base[(size_t)dd * (HW/4)];
        float4 v1 = base[(size_t)dd * (HW/4) + 1];
        d0x += v0.x * csh[la0+dd];  n0x += v0.x*v0.x;
        d0y += v0.y * csh[lb0+dd];  n0y += v0.y*v0.y;
        d0z += v0.z * csh[lc0+dd];  n0z += v0.z*v0.z;
        d0w += v0.w * csh[ld0+dd];  n0w += v0.w*v0.w;
        d1x += v1.x * csh[la1+dd];  n1x += v1.x*v1.x;
        d1y += v1.y * csh[lb1+dd];  n1y += v1.y*v1.y;
        d1z += v1.z * csh[lc1+dd];  n1z += v1.z*v1.z;
        d1w += v1.w * csh[ld1+dd];  n1w += v1.w*v1.w;
    }
    const int n = tile*1024 + (tid << 3);
    float4* dp = (float4*)&g_dotp[chunk*NPIX + n];
    float4* np = (float4*)&g_nsqp[chunk*NPIX + n];
    dp[0] = make_float4(d0x,d0y,d0z,d0w);
    dp[1] = make_float4(d1x,d1y,d1z,d1w);
    np[0] = make_float4(n0x,n0y,n0z,n0w);
    np[1] = make_float4(n1x,n1y,n1z,n1w);
}

// ---------------- kernel 4: per-pixel cos -> per-class (1-cos) sums ----------------
__global__ __launch_bounds__(256) void k_finalpix(const int* __restrict__ T) {
    __shared__ float bins[20];
    __shared__ float ncs[NC];
    const int tid = threadIdx.x;
    if (tid < 20) bins[tid] = 0.f;
    if (tid < NC) ncs[tid] = g_ncen[tid];
    __syncthreads();

    const int n = blockIdx.x*256 + tid;
    const int lab = T[n];
    float dot = 0.f, nsq = 0.f;
    #pragma unroll
    for (int c2 = 0; c2 < NCHUNK; c2++) {
        dot += g_dotp[c2*NPIX + n];
        nsq += g_nsqp[c2*NPIX + n];
    }
    float cosv = dot / fmaxf(sqrtf(nsq) * ncs[lab], EPS);
    atomicAdd(&bins[lab], 1.f - cosv);
    __syncthreads();
    if (tid < NC) atomicAdd(&g_percls[tid], bins[tid]);
}

// ---------------- kernel 5: finalize ----------------
__global__ void k_final(float* __restrict__ out) {
    float r = g_diff;
    for (int c = 0; c < NC; c++) {
        float cnt = g_counts[c];
        if (cnt > 0.f) r += g_percls[c] / fmaxf(cnt, 1.f);
    }
    out[0] = r;
}

extern "C" void kernel_launch(void* const* d_in, const int* in_sizes, int n_in,
                              void* d_out, int out_size) {
    const float4* X  = (const float4*)d_in[0];   // (8,256,128,128) fp32
    const int4*   T4 = (const int4*)d_in[1];     // (8,128,128) int32
    const int*    T  = (const int*)d_in[1];
    float* out = (float*)d_out;

    k_zero_counts<<<1, 32>>>();
    k_prep<<<NPIX/4/256, 256>>>(T4);
    k_pass1<<<NB*ND, 256>>>(X);
    k_diff<<<NC, 256>>>();
    k_pass2<<<(NPIX/1024)*NCHUNK, 128>>>(X, T4);
    k_finalpix<<<NPIX/256, 256>>>(T);
    k_final<<<1, 1>>>(out);
}

// round 13
// speedup vs baseline: 1.1326x; 1.1326x over previous
#include <cuda_runtime.h>
#include <math.h>

#define NC 19
#define ND 256
#define NB 8
#define HW 16384              // 128*128
#define NPIX (NB*HW)          // 131072
#define NCHUNK 8
#define DCH (ND/NCHUNK)       // 32
#define EPS 1e-8f
#define P2TILE 512
#define NHB 128               // k_prep blocks (histogram partials)

// ---------------- static scratch ----------------
__device__ float g_S[NC*ND];
__device__ float g_hist[NHB*NC];        // per-block label histograms
__device__ float g_counts[NC];
__device__ float g_centers[NC*ND];
__device__ float g_ncen[NC];
__device__ unsigned char g_lab8[NPIX];
__device__ float g_dotp[NCHUNK*NPIX];   // 4 MB
__device__ float g_nsqp[NCHUNK*NPIX];   // 4 MB
__device__ float g_percls[NC];
__device__ float g_diff;

// ---------------- kernel 0: prep — pack labels, partial hist, zero accum ----------------
// 128 blocks x 256 threads; thread handles one int4 (4 labels); NO global atomics
__global__ __launch_bounds__(256) void k_prep(const int4* __restrict__ T) {
    __shared__ int h[NC];
    const int t = threadIdx.x;
    if (t < NC) h[t] = 0;
    __syncthreads();
    const int i = blockIdx.x * 256 + t;          // 32768 int4s total
    int4 l = T[i];
    ((uchar4*)g_lab8)[i] = make_uchar4((unsigned char)l.x, (unsigned char)l.y,
                                       (unsigned char)l.z, (unsigned char)l.w);
    atomicAdd(&h[l.x], 1); atomicAdd(&h[l.y], 1);
    atomicAdd(&h[l.z], 1); atomicAdd(&h[l.w], 1);
    if (blockIdx.x == 0) {                       // zero g_S / g_percls (consumed later)
        for (int k = t; k < NC*ND; k += 256) g_S[k] = 0.f;
        if (t < NC) g_percls[t] = 0.f;
    }
    if (blockIdx.x == 1 && t == 0) g_diff = 0.f;
    __syncthreads();
    if (t < NC) g_hist[blockIdx.x*NC + t] = (float)h[t];
}

// ---------------- kernel 1: class sums, lane-private smem bins ----------------
__global__ __launch_bounds__(256) void k_pass1(const float4* __restrict__ X) {
    __shared__ float sbin[8*NC*32];       // 19456 B
    __shared__ float red[8*NC];
    const int t    = threadIdx.x;
    const int lane = t & 31;
    const int w    = t >> 5;
    const int b    = blockIdx.x >> 8;
    const int d    = blockIdx.x & 255;

    for (int i = t; i < 8*NC*32; i += 256) sbin[i] = 0.f;
    __syncthreads();

    const float4* plane = X + (size_t)(b*ND + d) * (HW/4);
    const uchar4* labs  = (const uchar4*)g_lab8 + (size_t)b * (HW/4);
    float* mybin = sbin + w*(NC*32) + lane;

    #pragma unroll 4
    for (int k = 0; k < 16; k++) {
        float4 v = plane[k*256 + t];
        uchar4 L = labs[k*256 + t];
        mybin[(int)L.x * 32] += v.x;
        mybin[(int)L.y * 32] += v.y;
        mybin[(int)L.z * 32] += v.z;
        mybin[(int)L.w * 32] += v.w;
    }
    __syncthreads();

    if (t < 8*NC) {
        const float* row = sbin + t*32;
        float s = 0.f;
        #pragma unroll
        for (int k = 0; k < 32; k++) s += row[(k + t) & 31];
        red[t] = s;
    }
    __syncthreads();
    if (t < NC) {
        float s = 0.f;
        #pragma unroll
        for (int ww = 0; ww < 8; ww++) s += red[ww*NC + t];
        atomicAdd(&g_S[t*ND + d], s);
    }
}

// ---------------- kernel 2a: counts + centers + norms, one block per class ----------------
__global__ __launch_bounds__(256) void k_centers() {
    __shared__ float red[8];
    __shared__ float cnt_sh;
    const int c    = blockIdx.x;           // 0..18
    const int tid  = threadIdx.x;          // == d index
    const int lane = tid & 31;
    const int w    = tid >> 5;

    // reduce 128 histogram partials (threads 0..127), 4 warps + smem
    float hv = (tid < NHB) ? g_hist[tid*NC + c] : 0.f;
    #pragma unroll
    for (int o = 16; o; o >>= 1) hv += __shfl_xor_sync(0xFFFFFFFFu, hv, o);
    if (lane == 0) red[w] = hv;
    __syncthreads();
    if (tid == 0) {
        float cnt = red[0]+red[1]+red[2]+red[3];
        cnt_sh = cnt;
        g_counts[c] = cnt;
    }
    __syncthreads();

    const float cnt = cnt_sh;
    float v = g_S[c*ND + tid] / fmaxf(cnt, 1.f);
    g_centers[c*ND + tid] = v;

    float s = v*v;
    #pragma unroll
    for (int o = 16; o; o >>= 1) s += __shfl_xor_sync(0xFFFFFFFFu, s, o);
    if (lane == 0) red[w] = s;
    __syncthreads();
    if (tid == 0) {
        float tot = red[0]+red[1]+red[2]+red[3]+red[4]+red[5]+red[6]+red[7];
        g_ncen[c] = sqrtf(tot);
    }
}

// ---------------- kernel 2b: diff_loss, one block per class i ----------------
__global__ __launch_bounds__(256) void k_diff() {
    __shared__ float ceni[ND];
    __shared__ float acc[8];
    const int i    = blockIdx.x;
    const int tid  = threadIdx.x;
    const int lane = tid & 31;
    const int w    = tid >> 5;

    ceni[tid] = g_centers[i*ND + tid];
    if (tid < 8) acc[tid] = 0.f;
    __syncthreads();

    const float ni = g_ncen[i];
    float mysum = 0.f;
    for (int j = w; j < NC; j += 8) {
        float dot = 0.f;
        #pragma unroll
        for (int dd = lane; dd < ND; dd += 32) dot += ceni[dd] * g_centers[j*ND + dd];
        #pragma unroll
        for (int o = 16; o; o >>= 1) dot += __shfl_xor_sync(0xFFFFFFFFu, dot, o);
        if (lane == 0) {
            float s = dot / fmaxf(ni * g_ncen[j], EPS);
            mysum += (i == j) ? (1.f - s) : fmaxf(s, 0.f);
        }
    }
    if (lane == 0) acc[w] = mysum;
    __syncthreads();
    if (tid == 0 && g_counts[i] > 0.f) {
        float tot = acc[0]+acc[1]+acc[2]+acc[3]+acc[4]+acc[5]+acc[6]+acc[7];
        atomicAdd(&g_diff, tot / (float)NC);
    }
}

// ---------------- kernel 3: per-pixel partial dot & normsq over a D-chunk ----------------
// 2048 blocks (256 tiles x 8 chunks), 128 threads, 4 pixels/thread (best measured)
__global__ __launch_bounds__(128) void k_pass2(const float4* __restrict__ X,
                                               const int4* __restrict__ T) {
    __shared__ float csh[NC*33];
    const int tid   = threadIdx.x;
    const int chunk = blockIdx.x & (NCHUNK-1);
    const int tile  = blockIdx.x >> 3;           // 0..255
    const int b     = tile >> 5;
    const int px0   = ((tile & 31) << 9) + (tid << 2);

    for (int i = tid; i < NC*DCH; i += 128) {
        int c = i / DCH, dd = i - c*DCH;
        csh[c*33 + dd] = g_centers[c*ND + chunk*DCH + dd];
    }
    __syncthreads();

    int4 l = T[((size_t)b*HW + px0) >> 2];
    const int la = l.x*33, lb = l.y*33, lc = l.z*33, ld = l.w*33;
    const float4* base = X + (size_t)(b*ND + chunk*DCH)*(HW/4) + (px0 >> 2);

    float dx=0,dy=0,dz=0,dw=0, nx=0,ny=0,nz=0,nw=0;
    #pragma unroll 8
    for (int dd = 0; dd < DCH; dd++) {
        float4 v = base[(size_t)dd * (HW/4)];
        dx += v.x * csh[la+dd];  nx += v.x*v.x;
        dy += v.y * csh[lb+dd];  ny += v.y*v.y;
        dz += v.z * csh[lc+dd];  nz += v.z*v.z;
        dw += v.w * csh[ld+dd];  nw += v.w*v.w;
    }
    const int n = tile*P2TILE + (tid << 2);
    *(float4*)&g_dotp[chunk*NPIX + n] = make_float4(dx,dy,dz,dw);
    *(float4*)&g_nsqp[chunk*NPIX + n] = make_float4(nx,ny,nz,nw);
}

// ---------------- kernel 4: per-pixel cos -> per-class (1-cos) sums ----------------
__global__ __launch_bounds__(256) void k_finalpix(const int* __restrict__ T) {
    __shared__ float bins[20];
    __shared__ float ncs[NC];
    const int tid = threadIdx.x;
    if (tid < 20) bins[tid] = 0.f;
    if (tid < NC) ncs[tid] = g_ncen[tid];
    __syncthreads();

    const int n = blockIdx.x*256 + tid;
    const int lab = T[n];
    float dot = 0.f, nsq = 0.f;
    #pragma unroll
    for (int c2 = 0; c2 < NCHUNK; c2++) {
        dot += g_dotp[c2*NPIX + n];
        nsq += g_nsqp[c2*NPIX + n];
    }
    float cosv = dot / fmaxf(sqrtf(nsq) * ncs[lab], EPS);
    atomicAdd(&bins[lab], 1.f - cosv);
    __syncthreads();
    if (tid < NC) atomicAdd(&g_percls[tid], bins[tid]);
}

// ---------------- kernel 5: finalize ----------------
__global__ void k_final(float* __restrict__ out) {
    float r = g_diff;
    for (int c = 0; c < NC; c++) {
        float cnt = g_counts[c];
        if (cnt > 0.f) r += g_percls[c] / fmaxf(cnt, 1.f);
    }
    out[0] = r;
}

extern "C" void kernel_launch(void* const* d_in, const int* in_sizes, int n_in,
                              void* d_out, int out_size) {
    const float4* X  = (const float4*)d_in[0];   // (8,256,128,128) fp32
    const int4*   T4 = (const int4*)d_in[1];     // (8,128,128) int32
    const int*    T  = (const int*)d_in[1];
    float* out = (float*)d_out;

    k_prep<<<NHB, 256>>>(T4);
    k_pass1<<<NB*ND, 256>>>(X);
    k_centers<<<NC, 256>>>();
    k_diff<<<NC, 256>>>();
    k_pass2<<<(NPIX/P2TILE)*NCHUNK, 128>>>(X, T4);
    k_finalpix<<<NPIX/256, 256>>>(T);
    k_final<<<1, 1>>>(out);
}

// round 16
// speedup vs baseline: 1.2661x; 1.1179x over previous
#include <cuda_runtime.h>
#include <math.h>

#define NC 19
#define ND 256
#define NB 8
#define HW 16384              // 128*128
#define NPIX (NB*HW)          // 131072
#define NCHUNK 8
#define DCH (ND/NCHUNK)       // 32
#define EPS 1e-8f
#define P2TILE 512
#define NHB 128               // k_prep blocks (histogram partials)

// ---------------- static scratch ----------------
__device__ float g_S[NC*ND];
__device__ float g_hist[NHB*NC];        // per-block label histograms
__device__ float g_counts[NC];
__device__ float g_centers[NC*ND];
__device__ float g_ncen[NC];
__device__ float g_dotmat[NC*NC];       // pairwise center dot products
__device__ unsigned char g_lab8[NPIX];
__device__ float g_dotp[NCHUNK*NPIX];   // 4 MB
__device__ float g_nsqp[NCHUNK*NPIX];   // 4 MB
__device__ float g_percls[NC];

// ---------------- kernel 0: prep — pack labels, partial hist, zero accum ----------------
__global__ __launch_bounds__(256) void k_prep(const int4* __restrict__ T) {
    __shared__ int h[NC];
    const int t = threadIdx.x;
    if (t < NC) h[t] = 0;
    __syncthreads();
    const int i = blockIdx.x * 256 + t;          // 32768 int4s total
    int4 l = T[i];
    ((uchar4*)g_lab8)[i] = make_uchar4((unsigned char)l.x, (unsigned char)l.y,
                                       (unsigned char)l.z, (unsigned char)l.w);
    atomicAdd(&h[l.x], 1); atomicAdd(&h[l.y], 1);
    atomicAdd(&h[l.z], 1); atomicAdd(&h[l.w], 1);
    if (blockIdx.x == 0) {                       // zero g_S / g_percls (consumed later)
        for (int k = t; k < NC*ND; k += 256) g_S[k] = 0.f;
        if (t < NC) g_percls[t] = 0.f;
    }
    __syncthreads();
    if (t < NC) g_hist[blockIdx.x*NC + t] = (float)h[t];
}

// ---------------- kernel 1: class sums, lane-private smem bins ----------------
__global__ __launch_bounds__(256) void k_pass1(const float4* __restrict__ X) {
    __shared__ float sbin[8*NC*32];       // 19456 B
    __shared__ float red[8*NC];
    const int t    = threadIdx.x;
    const int lane = t & 31;
    const int w    = t >> 5;
    const int b    = blockIdx.x >> 8;
    const int d    = blockIdx.x & 255;

    for (int i = t; i < 8*NC*32; i += 256) sbin[i] = 0.f;
    __syncthreads();

    const float4* plane = X + (size_t)(b*ND + d) * (HW/4);
    const uchar4* labs  = (const uchar4*)g_lab8 + (size_t)b * (HW/4);
    float* mybin = sbin + w*(NC*32) + lane;

    #pragma unroll 4
    for (int k = 0; k < 16; k++) {
        float4 v = plane[k*256 + t];
        uchar4 L = labs[k*256 + t];
        mybin[(int)L.x * 32] += v.x;
        mybin[(int)L.y * 32] += v.y;
        mybin[(int)L.z * 32] += v.z;
        mybin[(int)L.w * 32] += v.w;
    }
    __syncthreads();

    if (t < 8*NC) {
        const float* row = sbin + t*32;
        float s = 0.f;
        #pragma unroll
        for (int k = 0; k < 32; k++) s += row[(k + t) & 31];
        red[t] = s;
    }
    __syncthreads();
    if (t < NC) {
        float s = 0.f;
        #pragma unroll
        for (int ww = 0; ww < 8; ww++) s += red[ww*NC + t];
        atomicAdd(&g_S[t*ND + d], s);
    }
}

// ---------------- kernel 2: all-pairs center dots (+ diagonal publishes) ----------------
// grid = NC*NC = 361 blocks: one full wave, above the low-grid issue throttle
__global__ __launch_bounds__(256) void k_pairs() {
    __shared__ float redc[8];
    __shared__ float cnt_sh[2];
    __shared__ float redd[8];
    const int p   = blockIdx.x;
    const int i   = p / NC;
    const int j   = p - i*NC;
    const int tid = threadIdx.x;           // == d index
    const int lane = tid & 31;
    const int w    = tid >> 5;

    // counts: warps 0-3 reduce class i partials, warps 4-7 class j
    const int cls = (tid < 128) ? i : j;
    float hv = g_hist[(tid & 127)*NC + cls];
    #pragma unroll
    for (int o = 16; o; o >>= 1) hv += __shfl_xor_sync(0xFFFFFFFFu, hv, o);
    if (lane == 0) redc[w] = hv;
    __syncthreads();
    if (tid == 0) cnt_sh[0] = redc[0]+redc[1]+redc[2]+redc[3];
    if (tid == 1) cnt_sh[1] = redc[4]+redc[5]+redc[6]+redc[7];
    __syncthreads();
    const float cnt_i = cnt_sh[0], cnt_j = cnt_sh[1];

    const float ci = g_S[i*ND + tid] / fmaxf(cnt_i, 1.f);
    const float cj = g_S[j*ND + tid] / fmaxf(cnt_j, 1.f);
    float d = ci * cj;
    #pragma unroll
    for (int o = 16; o; o >>= 1) d += __shfl_xor_sync(0xFFFFFFFFu, d, o);
    if (lane == 0) redd[w] = d;
    __syncthreads();
    if (tid == 0) {
        float tot = redd[0]+redd[1]+redd[2]+redd[3]+redd[4]+redd[5]+redd[6]+redd[7];
        g_dotmat[p] = tot;
        if (i == j) { g_counts[i] = cnt_i; g_ncen[i] = sqrtf(tot); }
    }
    if (i == j) g_centers[i*ND + tid] = ci;
}

// ---------------- kernel 3: per-pixel partial dot & normsq over a D-chunk ----------------
__global__ __launch_bounds__(128) void k_pass2(const float4* __restrict__ X,
                                               const int4* __restrict__ T) {
    __shared__ float csh[NC*33];
    const int tid   = threadIdx.x;
    const int chunk = blockIdx.x & (NCHUNK-1);
    const int tile  = blockIdx.x >> 3;           // 0..255
    const int b     = tile >> 5;
    const int px0   = ((tile & 31) << 9) + (tid << 2);

    for (int i = tid; i < NC*DCH; i += 128) {
        int c = i / DCH, dd = i - c*DCH;
        csh[c*33 + dd] = g_centers[c*ND + chunk*DCH + dd];
    }
    __syncthreads();

    int4 l = T[((size_t)b*HW + px0) >> 2];
    const int la = l.x*33, lb = l.y*33, lc = l.z*33, ld = l.w*33;
    const float4* base = X + (size_t)(b*ND + chunk*DCH)*(HW/4) + (px0 >> 2);

    float dx=0,dy=0,dz=0,dw=0, nx=0,ny=0,nz=0,nw=0;
    #pragma unroll 8
    for (int dd = 0; dd < DCH; dd++) {
        float4 v = base[(size_t)dd * (HW/4)];
        dx += v.x * csh[la+dd];  nx += v.x*v.x;
        dy += v.y * csh[lb+dd];  ny += v.y*v.y;
        dz += v.z * csh[lc+dd];  nz += v.z*v.z;
        dw += v.w * csh[ld+dd];  nw += v.w*v.w;
    }
    const int n = tile*P2TILE + (tid << 2);
    *(float4*)&g_dotp[chunk*NPIX + n] = make_float4(dx,dy,dz,dw);
    *(float4*)&g_nsqp[chunk*NPIX + n] = make_float4(nx,ny,nz,nw);
}

// ---------------- kernel 4: per-pixel cos -> per-class (1-cos) sums ----------------
__global__ __launch_bounds__(256) void k_finalpix(const int* __restrict__ T) {
    __shared__ float bins[20];
    __shared__ float ncs[NC];
    const int tid = threadIdx.x;
    if (tid < 20) bins[tid] = 0.f;
    if (tid < NC) ncs[tid] = g_ncen[tid];
    __syncthreads();

    const int n = blockIdx.x*256 + tid;
    const int lab = T[n];
    float dot = 0.f, nsq = 0.f;
    #pragma unroll
    for (int c2 = 0; c2 < NCHUNK; c2++) {
        dot += g_dotp[c2*NPIX + n];
        nsq += g_nsqp[c2*NPIX + n];
    }
    float cosv = dot / fmaxf(sqrtf(nsq) * ncs[lab], EPS);
    atomicAdd(&bins[lab], 1.f - cosv);
    __syncthreads();
    if (tid < NC) atomicAdd(&g_percls[tid], bins[tid]);
}

// ---------------- kernel 5: finalize — diff from dotmat + sim from percls ----------------
__global__ __launch_bounds__(512) void k_final(float* __restrict__ out) {
    __shared__ float red[16];
    const int tid  = threadIdx.x;
    const int lane = tid & 31;
    const int w    = tid >> 5;

    float val = 0.f;
    if (tid < NC*NC) {                     // 361 pair terms
        const int i = tid / NC, j = tid - i*NC;
        const float cnt_i = g_counts[i];
        if (cnt_i > 0.f) {
            float s = g_dotmat[tid] / fmaxf(g_ncen[i]*g_ncen[j], EPS);
            val = ((i == j) ? (1.f - s) : fmaxf(s, 0.f)) / (float)NC;
        }
    }
    if (tid >= 384 && tid < 384 + NC) {    // 19 sim terms
        const int c = tid - 384;
        const float cnt = g_counts[c];
        if (cnt > 0.f) val += g_percls[c] / fmaxf(cnt, 1.f);
    }
    #pragma unroll
    for (int o = 16; o; o >>= 1) val += __shfl_xor_sync(0xFFFFFFFFu, val, o);
    if (lane == 0) red[w] = val;
    __syncthreads();
    if (tid == 0) {
        float r = 0.f;
        #pragma unroll
        for (int k = 0; k < 16; k++) r += red[k];
        out[0] = r;
    }
}

extern "C" void kernel_launch(void* const* d_in, const int* in_sizes, int n_in,
                              void* d_out, int out_size) {
    const float4* X  = (const float4*)d_in[0];   // (8,256,128,128) fp32
    const int4*   T4 = (const int4*)d_in[1];     // (8,128,128) int32
    const int*    T  = (const int*)d_in[1];
    float* out = (float*)d_out;

    k_prep<<<NHB, 256>>>(T4);
    k_pass1<<<NB*ND, 256>>>(X);
    k_pairs<<<NC*NC, 256>>>();
    k_pass2<<<(NPIX/P2TILE)*NCHUNK, 128>>>(X, T4);
    k_finalpix<<<NPIX/256, 256>>>(T);
    k_final<<<1, 512>>>(out);
}

// round 17
// speedup vs baseline: 1.2775x; 1.0090x over previous
#include <cuda_runtime.h>
#include <math.h>

#define NC 19
#define ND 256
#define NB 8
#define HW 16384              // 128*128
#define NPIX (NB*HW)          // 131072
#define NCHUNK 8
#define DCH (ND/NCHUNK)       // 32
#define EPS 1e-8f
#define NHB 256               // k_prep blocks (histogram partials), >=148

// ---------------- static scratch ----------------
__device__ float g_S[NC*ND];
__device__ float g_hist[NHB*NC];        // per-block label histograms
__device__ float g_counts[NC];
__device__ float g_centers[NC*ND];
__device__ float g_ncen[NC];
__device__ float g_dotmat[NC*NC];       // pairwise center dot products
__device__ unsigned char g_lab8[NPIX];
__device__ float g_dotp[NCHUNK*NPIX];   // 4 MB
__device__ float g_nsqp[NCHUNK*NPIX];   // 4 MB
__device__ float g_percls[NC];

// ---------------- kernel 0: prep — pack labels, partial hist, zero accum ----------------
// 256 blocks x 128 threads (grid >= 148: above low-grid issue throttle)
__global__ __launch_bounds__(128) void k_prep(const int4* __restrict__ T) {
    __shared__ int h[NC];
    const int t = threadIdx.x;
    if (t < NC) h[t] = 0;
    __syncthreads();
    const int i = blockIdx.x * 128 + t;          // 32768 int4s total
    int4 l = T[i];
    ((uchar4*)g_lab8)[i] = make_uchar4((unsigned char)l.x, (unsigned char)l.y,
                                       (unsigned char)l.z, (unsigned char)l.w);
    atomicAdd(&h[l.x], 1); atomicAdd(&h[l.y], 1);
    atomicAdd(&h[l.z], 1); atomicAdd(&h[l.w], 1);
    if (blockIdx.x == 0) {                       // zero g_S / g_percls (consumed later)
        for (int k = t; k < NC*ND; k += 128) g_S[k] = 0.f;
        if (t < NC) g_percls[t] = 0.f;
    }
    __syncthreads();
    if (t < NC) g_hist[blockIdx.x*NC + t] = (float)h[t];
}

// ---------------- kernel 1: class sums, lane-private smem bins ----------------
__global__ __launch_bounds__(256) void k_pass1(const float4* __restrict__ X) {
    __shared__ float sbin[8*NC*32];       // 19456 B
    __shared__ float red[8*NC];
    const int t    = threadIdx.x;
    const int lane = t & 31;
    const int w    = t >> 5;
    const int b    = blockIdx.x >> 8;
    const int d    = blockIdx.x & 255;

    for (int i = t; i < 8*NC*32; i += 256) sbin[i] = 0.f;
    __syncthreads();

    const float4* plane = X + (size_t)(b*ND + d) * (HW/4);
    const uchar4* labs  = (const uchar4*)g_lab8 + (size_t)b * (HW/4);
    float* mybin = sbin + w*(NC*32) + lane;

    #pragma unroll 4
    for (int k = 0; k < 16; k++) {
        float4 v = plane[k*256 + t];
        uchar4 L = labs[k*256 + t];
        mybin[(int)L.x * 32] += v.x;
        mybin[(int)L.y * 32] += v.y;
        mybin[(int)L.z * 32] += v.z;
        mybin[(int)L.w * 32] += v.w;
    }
    __syncthreads();

    if (t < 8*NC) {
        const float* row = sbin + t*32;
        float s = 0.f;
        #pragma unroll
        for (int k = 0; k < 32; k++) s += row[(k + t) & 31];
        red[t] = s;
    }
    __syncthreads();
    if (t < NC) {
        float s = 0.f;
        #pragma unroll
        for (int ww = 0; ww < 8; ww++) s += red[ww*NC + t];
        atomicAdd(&g_S[t*ND + d], s);
    }
}

// ---------------- kernel 2: all-pairs center dots (+ diagonal publishes) ----------------
// grid = NC*NC = 361 blocks: one full wave, above the low-grid issue throttle
__global__ __launch_bounds__(256) void k_pairs() {
    __shared__ float redc[8];
    __shared__ float cnt_sh[2];
    __shared__ float redd[8];
    const int p   = blockIdx.x;
    const int i   = p / NC;
    const int j   = p - i*NC;
    const int tid = threadIdx.x;           // == d index
    const int lane = tid & 31;
    const int w    = tid >> 5;

    // counts: warps 0-3 reduce class i partials (2 each), warps 4-7 class j
    const int cls = (tid < 128) ? i : j;
    float hv = g_hist[(tid & 127)*NC + cls] + g_hist[((tid & 127) + 128)*NC + cls];
    #pragma unroll
    for (int o = 16; o; o >>= 1) hv += __shfl_xor_sync(0xFFFFFFFFu, hv, o);
    if (lane == 0) redc[w] = hv;
    __syncthreads();
    if (tid == 0) cnt_sh[0] = redc[0]+redc[1]+redc[2]+redc[3];
    if (tid == 1) cnt_sh[1] = redc[4]+redc[5]+redc[6]+redc[7];
    __syncthreads();
    const float cnt_i = cnt_sh[0], cnt_j = cnt_sh[1];

    const float ci = g_S[i*ND + tid] / fmaxf(cnt_i, 1.f);
    const float cj = g_S[j*ND + tid] / fmaxf(cnt_j, 1.f);
    float d = ci * cj;
    #pragma unroll
    for (int o = 16; o; o >>= 1) d += __shfl_xor_sync(0xFFFFFFFFu, d, o);
    if (lane == 0) redd[w] = d;
    __syncthreads();
    if (tid == 0) {
        float tot = redd[0]+redd[1]+redd[2]+redd[3]+redd[4]+redd[5]+redd[6]+redd[7];
        g_dotmat[p] = tot;
        if (i == j) { g_counts[i] = cnt_i; g_ncen[i] = sqrtf(tot); }
    }
    if (i == j) g_centers[i*ND + tid] = ci;
}

// ---------------- kernel 3: per-pixel partial dot & normsq over a D-chunk ----------------
// 256 threads, 1024-px tiles, 8 chunks -> 1024 blocks; 4 KB contiguous per dd iter
__global__ __launch_bounds__(256) void k_pass2(const float4* __restrict__ X,
                                               const int4* __restrict__ T) {
    __shared__ float csh[NC*33];
    const int tid   = threadIdx.x;
    const int chunk = blockIdx.x & (NCHUNK-1);
    const int tile  = blockIdx.x >> 3;           // 0..127, 1024 px each
    const int b     = tile >> 4;                 // 16 tiles per batch
    const int px0   = ((tile & 15) << 10) + (tid << 2);

    for (int i = tid; i < NC*DCH; i += 256) {
        int c = i / DCH, dd = i - c*DCH;
        csh[c*33 + dd] = g_centers[c*ND + chunk*DCH + dd];
    }
    __syncthreads();

    int4 l = T[((size_t)b*HW + px0) >> 2];
    const int la = l.x*33, lb = l.y*33, lc = l.z*33, ld = l.w*33;
    const float4* base = X + (size_t)(b*ND + chunk*DCH)*(HW/4) + (px0 >> 2);

    float dx=0,dy=0,dz=0,dw=0, nx=0,ny=0,nz=0,nw=0;
    #pragma unroll 8
    for (int dd = 0; dd < DCH; dd++) {
        float4 v = base[(size_t)dd * (HW/4)];
        dx += v.x * csh[la+dd];  nx += v.x*v.x;
        dy += v.y * csh[lb+dd];  ny += v.y*v.y;
        dz += v.z * csh[lc+dd];  nz += v.z*v.z;
        dw += v.w * csh[ld+dd];  nw += v.w*v.w;
    }
    const int n = tile*1024 + (tid << 2);
    *(float4*)&g_dotp[chunk*NPIX + n] = make_float4(dx,dy,dz,dw);
    *(float4*)&g_nsqp[chunk*NPIX + n] = make_float4(nx,ny,nz,nw);
}

// ---------------- kernel 4: per-pixel cos -> per-class (1-cos) sums ----------------
__global__ __launch_bounds__(256) void k_finalpix(const int* __restrict__ T) {
    __shared__ float bins[20];
    __shared__ float ncs[NC];
    const int tid = threadIdx.x;
    if (tid < 20) bins[tid] = 0.f;
    if (tid < NC) ncs[tid] = g_ncen[tid];
    __syncthreads();

    const int n = blockIdx.x*256 + tid;
    const int lab = T[n];
    float dot = 0.f, nsq = 0.f;
    #pragma unroll
    for (int c2 = 0; c2 < NCHUNK; c2++) {
        dot += g_dotp[c2*NPIX + n];
        nsq += g_nsqp[c2*NPIX + n];
    }
    float cosv = dot / fmaxf(sqrtf(nsq) * ncs[lab], EPS);
    atomicAdd(&bins[lab], 1.f - cosv);
    __syncthreads();
    if (tid < NC) atomicAdd(&g_percls[tid], bins[tid]);
}

// ---------------- kernel 5: finalize — diff from dotmat + sim from percls ----------------
__global__ __launch_bounds__(512) void k_final(float* __restrict__ out) {
    __shared__ float red[16];
    const int tid  = threadIdx.x;
    const int lane = tid & 31;
    const int w    = tid >> 5;

    float val = 0.f;
    if (tid < NC*NC) {                     // 361 pair terms
        const int i = tid / NC, j = tid - i*NC;
        const float cnt_i = g_counts[i];
        if (cnt_i > 0.f) {
            float s = g_dotmat[tid] / fmaxf(g_ncen[i]*g_ncen[j], EPS);
            val = ((i == j) ? (1.f - s) : fmaxf(s, 0.f)) / (float)NC;
        }
    }
    if (tid >= 384 && tid < 384 + NC) {    // 19 sim terms
        const int c = tid - 384;
        const float cnt = g_counts[c];
        if (cnt > 0.f) val += g_percls[c] / fmaxf(cnt, 1.f);
    }
    #pragma unroll
    for (int o = 16; o; o >>= 1) val += __shfl_xor_sync(0xFFFFFFFFu, val, o);
    if (lane == 0) red[w] = val;
    __syncthreads();
    if (tid == 0) {
        float r = 0.f;
        #pragma unroll
        for (int k = 0; k < 16; k++) r += red[k];
        out[0] = r;
    }
}

extern "C" void kernel_launch(void* const* d_in, const int* in_sizes, int n_in,
                              void* d_out, int out_size) {
    const float4* X  = (const float4*)d_in[0];   // (8,256,128,128) fp32
    const int4*   T4 = (const int4*)d_in[1];     // (8,128,128) int32
    const int*    T  = (const int*)d_in[1];
    float* out = (float*)d_out;

    k_prep<<<NHB, 128>>>(T4);
    k_pass1<<<NB*ND, 256>>>(X);
    k_pairs<<<NC*NC, 256>>>();
    k_pass2<<<(NPIX/1024)*NCHUNK, 256>>>(X, T4);
    k_finalpix<<<NPIX/256, 256>>>(T);
    k_final<<<1, 512>>>(out);
}